// round 14
// baseline (speedup 1.0000x reference)
#include <cuda_runtime.h>
#include <cstring>

#define TH 0.5f

using ull = unsigned long long;

struct Params {
    uint4 SPb[17];  // base spike patterns (j=0): bit 8*(t&3) of word t>>2 set iff (t+1)%n==0
    float tt[16];   // exact breakpoints, strictly decreasing: tt[k] = min fp32 c with u_{k+1}(c) >= TH
};

// ---- dynamic smem layout (all hot reads conflict-free via r = lane&7 copy) ----
static const int SM_A   = 0;                   // table half A: entry m at m*128 + r*16   (32768)
static const int SM_B   = 32768;               // table half B                            (32768)
static const int SM_SP  = 65536;               // pre-shifted patterns: (n1*8+j)*128+r*16 (17408)
static const int SM_TTG = SM_SP + 17408;       // tt groups of 4: g*128 + r*16            (512)
static const int SM_WP  = SM_TTG + 512;        // packed W_ih/b_ih channel-pair splats    (128)
static const int SMEM_BYTES = SM_WP + 128;     // 83584

// ---- packed f32x2 helpers: per-lane fp32 rn, bitwise == scalar ops ----
__device__ __forceinline__ ull pk(float lo, float hi) {
    ull r; asm("mov.b64 %0, {%1, %2};" : "=l"(r) : "f"(lo), "f"(hi)); return r;
}
__device__ __forceinline__ void upk(float& lo, float& hi, ull v) {
    asm("mov.b64 {%0, %1}, %2;" : "=f"(lo), "=f"(hi) : "l"(v));
}
__device__ __forceinline__ ull mul2(ull a, ull b) {
    ull d; asm("mul.rn.f32x2 %0, %1, %2;" : "=l"(d) : "l"(a), "l"(b)); return d;
}
__device__ __forceinline__ ull add2(ull a, ull b) {
    ull d; asm("add.rn.f32x2 %0, %1, %2;" : "=l"(d) : "l"(a), "l"(b)); return d;
}
__device__ __forceinline__ ull fma2(ull a, ull b, ull c) {
    ull d; asm("fma.rn.f32x2 %0, %1, %2, %3;" : "=l"(d) : "l"(a), "l"(b), "l"(c)); return d;
}

__global__ __launch_bounds__(256, 2) void snn_kernel(
    const float4* __restrict__ x2,      // adjacent element pairs
    const float* __restrict__ W_ih,
    const float* __restrict__ b_ih,
    const float* __restrict__ W_hh,
    const float* __restrict__ b_hh,
    const float* __restrict__ W_ho,
    const float* __restrict__ b_ho,
    float2* __restrict__ out,
    int NP, Params P)
{
    extern __shared__ __align__(128) char sm[];
    int tid = threadIdx.x;

    // ---- prologue: per-block table build (values bitwise == round-5/6 build) ----
    {
        float ent[8];
#pragma unroll
        for (int j = 0; j < 8; j++) {
            float s = 0.f;
#pragma unroll
            for (int i = 0; i < 8; i++)
                s = __fadd_rn(s, ((tid >> i) & 1) ? W_hh[j * 8 + i] : 0.f);
            ent[j] = __fadd_rn(s, b_hh[j]);
        }
        float4 ea = make_float4(ent[0], ent[1], ent[2], ent[3]);
        float4 eb = make_float4(ent[4], ent[5], ent[6], ent[7]);
#pragma unroll
        for (int p = 0; p < 8; p++) {
            int r = (tid + p) & 7;
            *(float4*)(sm + SM_A + tid * 128 + r * 16) = ea;
            *(float4*)(sm + SM_B + tid * 128 + r * 16) = eb;
        }
    }
    for (int i = tid; i < 136 * 8; i += 256) {   // pre-shifted patterns, 8 copies
        int e = i >> 3, r = i & 7;
        int n1 = e >> 3, j = e & 7;
        uint4 b = P.SPb[n1];
        *(uint4*)(sm + SM_SP + e * 128 + r * 16) =
            make_uint4(b.x << j, b.y << j, b.z << j, b.w << j);
    }
    if (tid < 32) {                              // tt groups of 4, 8 copies
        int g = tid >> 3, r = tid & 7;
        *(float4*)(sm + SM_TTG + g * 128 + r * 16) =
            make_float4(P.tt[4 * g], P.tt[4 * g + 1], P.tt[4 * g + 2], P.tt[4 * g + 3]);
    }
    if (tid < 4) {                               // channel-pair splats of W_ih / b_ih
        int p2 = tid;
        ((float2*)(sm + SM_WP))[p2]      = make_float2(W_ih[4 * p2],     W_ih[4 * p2 + 2]);
        ((float2*)(sm + SM_WP + 32))[p2] = make_float2(W_ih[4 * p2 + 1], W_ih[4 * p2 + 3]);
        ((float2*)(sm + SM_WP + 64))[p2] = make_float2(b_ih[2 * p2],     b_ih[2 * p2 + 1]);
    }
    __syncthreads();

    const char* tA   = sm + SM_A   + (tid & 7) * 16;
    const char* tB   = sm + SM_B   + (tid & 7) * 16;
    const char* tSP  = sm + SM_SP  + (tid & 7) * 16;
    const char* tTTG = sm + SM_TTG + (tid & 7) * 16;

    float who[8];
#pragma unroll
    for (int j = 0; j < 8; j++) who[j] = W_ho[j];
    float bo = b_ho[0];

    const ull L2 = 0x3F4CCCCD3F4CCCCDULL;  // {0.8f, 0.8f}

    int TOT = gridDim.x * 256;
    int g = blockIdx.x * 256 + tid;

    // Software-pipelined grid-stride: next iteration's input loaded early.
    float4 xx;
    if (g < NP) xx = x2[g];

    while (g < NP) {
        int gn = g + TOT;
        float4 xn;
        if (gn < NP) xn = x2[gn];   // prefetch next iteration's pair

        // ---- Layer 1 for both elements: packed c, two-level exact count ----
        unsigned Mw[2][4] = {{0,0,0,0},{0,0,0,0}};
#pragma unroll
        for (int el = 0; el < 2; el++) {
            float X0 = el ? xx.z : xx.x;
            float X1 = el ? xx.w : xx.y;
            ull x0s = pk(X0, X0), x1s = pk(X1, X1);
#pragma unroll
            for (int p2 = 0; p2 < 4; p2++) {
                ull w0p = *(const ull*)(sm + SM_WP +      p2 * 8);
                ull w1p = *(const ull*)(sm + SM_WP + 32 + p2 * 8);
                ull bp  = *(const ull*)(sm + SM_WP + 64 + p2 * 8);
                // per-lane: rn(rn(rn(x0*w0) + rn(x1*w1)) + b) — same as round 5
                ull c2 = add2(add2(mul2(x0s, w0p), mul2(x1s, w1p)), bp);
                float cf[2]; upk(cf[0], cf[1], c2);
#pragma unroll
                for (int h = 0; h < 2; h++) {
                    float c = cf[h];
                    int j = 2 * p2 + h;
                    // coarse: pick group of 4 (pivot compares use constant-bank operands)
                    int nb = ((c < P.tt[3])  ? 4 : 0)
                           + ((c < P.tt[7])  ? 4 : 0)
                           + ((c < P.tt[11]) ? 4 : 0);
                    float4 gq = *(const float4*)(tTTG + nb * 32);
                    int n1 = nb + ((c < gq.x) ? 1 : 0) + ((c < gq.y) ? 1 : 0)
                                + ((c < gq.z) ? 1 : 0) + ((c < gq.w) ? 1 : 0);
                    uint4 pb = *(const uint4*)(tSP + (n1 * 8 + j) * 128);
                    Mw[el][0] |= pb.x; Mw[el][1] |= pb.y;
                    Mw[el][2] |= pb.z; Mw[el][3] |= pb.w;
                }
            }
        }

        // ---- Layers 2 + 3, both elements interleaved for ILP.
        //      Table rows double-buffered one step ahead: step t+1's LDS issue
        //      before step t's arithmetic -> 29-cyc LDS latency fully covered. ----
        ull m2p[2][4];
#pragma unroll
        for (int k = 0; k < 4; k++) { m2p[0][k] = 0ULL; m2p[1][k] = 0ULL; }
        float mo[2] = {0.f, 0.f}, cnt[2] = {0.f, 0.f};

        float4 Ac[2], Bc[2];
#pragma unroll
        for (int el = 0; el < 2; el++) {
            unsigned mk0 = __byte_perm(Mw[el][0], 0u, 0x4440);
            Ac[el] = *(const float4*)(tA + mk0 * 128);
            Bc[el] = *(const float4*)(tB + mk0 * 128);
        }

#pragma unroll
        for (int t = 0; t < 16; t++) {
            float4 An[2], Bn[2];
            if (t < 15) {
#pragma unroll
                for (int el = 0; el < 2; el++) {
                    unsigned mkn = __byte_perm(Mw[el][(t + 1) >> 2], 0u,
                                               0x4440 | ((t + 1) & 3));
                    An[el] = *(const float4*)(tA + mkn * 128);
                    Bn[el] = *(const float4*)(tB + mkn * 128);
                }
            }
#pragma unroll
            for (int el = 0; el < 2; el++) {
                ull tp[4] = {pk(Ac[el].x, Ac[el].y), pk(Ac[el].z, Ac[el].w),
                             pk(Bc[el].x, Bc[el].y), pk(Bc[el].z, Bc[el].w)};

                float acc = 0.f;
#pragma unroll
                for (int k = 0; k < 4; k++) {
                    ull v2 = fma2(L2, m2p[el][k], tp[k]);   // per-lane fmaf(0.8, m2, tt)
                    float vl, vh; upk(vl, vh, v2);
                    bool sl = (vl >= TH);
                    if (sl) acc += who[2 * k];
                    vl = sl ? 0.f : vl;
                    bool sh = (vh >= TH);
                    if (sh) acc += who[2 * k + 1];
                    vh = sh ? 0.f : vh;
                    m2p[el][k] = pk(vl, vh);
                }

                float vo = __fadd_rn(fmaf(0.8f, mo[el], acc), bo);
                bool so = (vo >= TH);
                cnt[el] += so ? 1.f : 0.f;
                mo[el] = so ? 0.f : vo;
            }
            if (t < 15) {
#pragma unroll
                for (int el = 0; el < 2; el++) { Ac[el] = An[el]; Bc[el] = Bn[el]; }
            }
        }

        out[g] = make_float2(cnt[0] * 0.0625f, cnt[1] * 0.0625f);

        g = gn;
        xx = xn;
    }
}

// Host-side replica of the device fp32 iteration (volatile blocks FMA contraction).
static float host_sim(float c, int n) {
    volatile float u = 0.f;
    for (int k = 0; k < n; k++) { volatile float t = 0.8f * u; u = t + c; }
    return u;
}

extern "C" void kernel_launch(void* const* d_in, const int* in_sizes, int n_in,
                              void* d_out, int out_size) {
    const float4* x2  = (const float4*)d_in[0];
    const float* W_ih = (const float*)d_in[1];
    const float* b_ih = (const float*)d_in[2];
    const float* W_hh = (const float*)d_in[3];
    const float* b_hh = (const float*)d_in[4];
    const float* W_ho = (const float*)d_in[5];
    const float* b_ho = (const float*)d_in[6];

    int B = in_sizes[0] / 2;
    int NP = B / 2;

    Params P;
    // Exact breakpoints via bitwise bisection (monotone in float bits on [0.05, 4]).
    for (int n = 1; n <= 16; n++) {
        float flo = 0.05f, fhi = 4.0f;
        unsigned lo, hi;
        memcpy(&lo, &flo, 4); memcpy(&hi, &fhi, 4);
        while (hi - lo > 1u) {
            unsigned mid = lo + (hi - lo) / 2;
            float fm; memcpy(&fm, &mid, 4);
            if (host_sim(fm, n) >= TH) hi = mid; else lo = mid;
        }
        memcpy(&P.tt[n - 1], &hi, 4);
    }
    for (int n1 = 0; n1 < 17; n1++) {
        unsigned w[4] = {0u, 0u, 0u, 0u};
        int n = n1 + 1;
        if (n <= 16)
            for (int t = 0; t < 16; t++)
                if ((t + 1) % n == 0) w[t >> 2] |= 1u << (8 * (t & 3));
        P.SPb[n1] = make_uint4(w[0], w[1], w[2], w[3]);
    }

    cudaFuncSetAttribute(snn_kernel,
                         cudaFuncAttributeMaxDynamicSharedMemorySize, SMEM_BYTES);

    snn_kernel<<<296, 256, SMEM_BYTES>>>(x2, W_ih, b_ih, W_hh, b_hh, W_ho, b_ho,
                                         (float2*)d_out, NP, P);
}

// round 15
// speedup vs baseline: 1.0247x; 1.0247x over previous
#include <cuda_runtime.h>
#include <cstring>

#define TH 0.5f

using ull = unsigned long long;

struct Params {
    uint4 SPb[17];  // base spike patterns (j=0): bit 8*(t&3) of word t>>2 set iff (t+1)%n==0
    float tt[16];   // exact breakpoints, strictly decreasing: tt[k] = min fp32 c with u_{k+1}(c) >= TH
};

// Bucket-LUT geometry: buckets of 2^16 ULP over [0x3DB80000, 0x3F05FFFF].
// Smallest breakpoint gap is ~169k ULP > 65536 -> at most one breakpoint/bucket.
#define NL_BASE  0x3DB8u
#define NL_N     334            // 0x3F06 - 0x3DB8
#define NL_CLO   __uint_as_float(0x3DB80000u)   // < tt[15]
#define NL_CHI   __uint_as_float(0x3F05FFFFu)   // > tt[0] = 0.5

// ---- dynamic smem layout (pattern reads conflict-free via r = lane&7 copy) ----
static const int SM_A   = 0;                   // table half A: entry m at m*128 + r*16   (32768)
static const int SM_B   = 32768;               // table half B                            (32768)
static const int SM_SP  = 65536;               // pre-shifted patterns: (n1*8+j)*128+r*16 (17408)
static const int SM_NL  = SM_SP + 17408;       // bucket LUT: idx*16 = {thr,offLo,offHi,0}(5344)
static const int SM_WP  = SM_NL + NL_N * 16;   // packed W_ih/b_ih channel-pair splats    (128)
static const int SMEM_BYTES = SM_WP + 128;     // 88416

// ---- packed f32x2 helpers: per-lane fp32 rn, bitwise == scalar ops ----
__device__ __forceinline__ ull pk(float lo, float hi) {
    ull r; asm("mov.b64 %0, {%1, %2};" : "=l"(r) : "f"(lo), "f"(hi)); return r;
}
__device__ __forceinline__ void upk(float& lo, float& hi, ull v) {
    asm("mov.b64 {%0, %1}, %2;" : "=f"(lo), "=f"(hi) : "l"(v));
}
__device__ __forceinline__ ull mul2(ull a, ull b) {
    ull d; asm("mul.rn.f32x2 %0, %1, %2;" : "=l"(d) : "l"(a), "l"(b)); return d;
}
__device__ __forceinline__ ull add2(ull a, ull b) {
    ull d; asm("add.rn.f32x2 %0, %1, %2;" : "=l"(d) : "l"(a), "l"(b)); return d;
}
__device__ __forceinline__ ull fma2(ull a, ull b, ull c) {
    ull d; asm("fma.rn.f32x2 %0, %1, %2, %3;" : "=l"(d) : "l"(a), "l"(b), "l"(c)); return d;
}

__global__ __launch_bounds__(256, 2) void snn_kernel(
    const float4* __restrict__ x2,      // adjacent element pairs
    const float* __restrict__ W_ih,
    const float* __restrict__ b_ih,
    const float* __restrict__ W_hh,
    const float* __restrict__ b_hh,
    const float* __restrict__ W_ho,
    const float* __restrict__ b_ho,
    float2* __restrict__ out,
    int NP, Params P)
{
    extern __shared__ __align__(128) char sm[];
    int tid = threadIdx.x;

    // ---- prologue: per-block table build (values bitwise == round-5/6 build) ----
    {
        float ent[8];
#pragma unroll
        for (int j = 0; j < 8; j++) {
            float s = 0.f;
#pragma unroll
            for (int i = 0; i < 8; i++)
                s = __fadd_rn(s, ((tid >> i) & 1) ? W_hh[j * 8 + i] : 0.f);
            ent[j] = __fadd_rn(s, b_hh[j]);
        }
        float4 ea = make_float4(ent[0], ent[1], ent[2], ent[3]);
        float4 eb = make_float4(ent[4], ent[5], ent[6], ent[7]);
#pragma unroll
        for (int p = 0; p < 8; p++) {
            int r = (tid + p) & 7;
            *(float4*)(sm + SM_A + tid * 128 + r * 16) = ea;
            *(float4*)(sm + SM_B + tid * 128 + r * 16) = eb;
        }
    }
    for (int i = tid; i < 136 * 8; i += 256) {   // pre-shifted patterns, 8 copies
        int e = i >> 3, r = i & 7;
        int n1 = e >> 3, j = e & 7;
        uint4 b = P.SPb[n1];
        *(uint4*)(sm + SM_SP + e * 128 + r * 16) =
            make_uint4(b.x << j, b.y << j, b.z << j, b.w << j);
    }
    // Bucket LUT: entry = {thr_bits, off_below, off_above, 0}; off = n1 * 1024
    // (pattern-table byte offset). At most one breakpoint per bucket (proven by
    // ULP spacing), so one compare against thr reproduces the exact count.
    for (int i = tid; i < NL_N; i += 256) {
        unsigned lob = (NL_BASE + (unsigned)i) << 16;
        float a   = __uint_as_float(lob);
        float bmx = __uint_as_float(lob | 0xFFFFu);
        int n1a = 0, n1b = 0;
#pragma unroll
        for (int k = 0; k < 16; k++) {
            n1a += (a   < P.tt[k]) ? 1 : 0;
            n1b += (bmx < P.tt[k]) ? 1 : 0;
        }
        unsigned thr = (n1a != n1b) ? __float_as_uint(P.tt[n1b]) : 0u;
        *(uint4*)(sm + SM_NL + i * 16) =
            make_uint4(thr, (unsigned)n1a * 1024u, (unsigned)n1b * 1024u, 0u);
    }
    if (tid < 4) {                               // channel-pair splats of W_ih / b_ih
        int p2 = tid;
        ((float2*)(sm + SM_WP))[p2]      = make_float2(W_ih[4 * p2],     W_ih[4 * p2 + 2]);
        ((float2*)(sm + SM_WP + 32))[p2] = make_float2(W_ih[4 * p2 + 1], W_ih[4 * p2 + 3]);
        ((float2*)(sm + SM_WP + 64))[p2] = make_float2(b_ih[2 * p2],     b_ih[2 * p2 + 1]);
    }
    __syncthreads();

    const char* tA  = sm + SM_A  + (tid & 7) * 16;
    const char* tB  = sm + SM_B  + (tid & 7) * 16;
    const char* tSP = sm + SM_SP + (tid & 7) * 16;

    float who[8];
#pragma unroll
    for (int j = 0; j < 8; j++) who[j] = W_ho[j];
    float bo = b_ho[0];

    const ull L2 = 0x3F4CCCCD3F4CCCCDULL;  // {0.8f, 0.8f}

    int TOT = gridDim.x * 256;
    int g = blockIdx.x * 256 + tid;

    // Software-pipelined grid-stride: next iteration's input loaded early.
    float4 xx;
    if (g < NP) xx = x2[g];

    while (g < NP) {
        int gn = g + TOT;
        float4 xn;
        if (gn < NP) xn = x2[gn];   // prefetch next iteration's pair

        // ---- Layer 1 for both elements: packed c, bucket-LUT exact count ----
        unsigned Mw[2][4] = {{0,0,0,0},{0,0,0,0}};
#pragma unroll
        for (int el = 0; el < 2; el++) {
            float X0 = el ? xx.z : xx.x;
            float X1 = el ? xx.w : xx.y;
            ull x0s = pk(X0, X0), x1s = pk(X1, X1);
#pragma unroll
            for (int p2 = 0; p2 < 4; p2++) {
                ull w0p = *(const ull*)(sm + SM_WP +      p2 * 8);
                ull w1p = *(const ull*)(sm + SM_WP + 32 + p2 * 8);
                ull bp  = *(const ull*)(sm + SM_WP + 64 + p2 * 8);
                // per-lane: rn(rn(rn(x0*w0) + rn(x1*w1)) + b) — same as round 5
                ull c2 = add2(add2(mul2(x0s, w0p), mul2(x1s, w1p)), bp);
                float cf[2]; upk(cf[0], cf[1], c2);
#pragma unroll
                for (int h = 0; h < 2; h++) {
                    float c = cf[h];
                    int j = 2 * p2 + h;
                    // Clamp is exact: outside [CLO, CHI] the bucket has no
                    // breakpoint, so the compare outcome is irrelevant there.
                    float cc = fminf(fmaxf(c, NL_CLO), NL_CHI);
                    unsigned idx = (__float_as_uint(cc) >> 16) - NL_BASE;
                    uint4 e = *(const uint4*)(sm + SM_NL + idx * 16);
                    unsigned off = (cc < __uint_as_float(e.x)) ? e.y : e.z;
                    uint4 pb = *(const uint4*)(tSP + j * 128 + off);
                    Mw[el][0] |= pb.x; Mw[el][1] |= pb.y;
                    Mw[el][2] |= pb.z; Mw[el][3] |= pb.w;
                }
            }
        }

        // ---- Layers 2 + 3, both elements interleaved for ILP (round-13 form) ----
        ull m2p[2][4];
#pragma unroll
        for (int k = 0; k < 4; k++) { m2p[0][k] = 0ULL; m2p[1][k] = 0ULL; }
        float mo[2] = {0.f, 0.f}, cnt[2] = {0.f, 0.f};

#pragma unroll
        for (int t = 0; t < 16; t++) {
#pragma unroll
            for (int el = 0; el < 2; el++) {
                unsigned mk = __byte_perm(Mw[el][t >> 2], 0u, 0x4440 | (t & 3));
                float4 A  = *(const float4*)(tA + mk * 128);
                float4 Bv = *(const float4*)(tB + mk * 128);
                ull tp[4] = {pk(A.x, A.y), pk(A.z, A.w), pk(Bv.x, Bv.y), pk(Bv.z, Bv.w)};

                float acc = 0.f;
#pragma unroll
                for (int k = 0; k < 4; k++) {
                    ull v2 = fma2(L2, m2p[el][k], tp[k]);   // per-lane fmaf(0.8, m2, tt)
                    float vl, vh; upk(vl, vh, v2);
                    bool sl = (vl >= TH);
                    if (sl) acc += who[2 * k];
                    vl = sl ? 0.f : vl;
                    bool sh = (vh >= TH);
                    if (sh) acc += who[2 * k + 1];
                    vh = sh ? 0.f : vh;
                    m2p[el][k] = pk(vl, vh);
                }

                float vo = __fadd_rn(fmaf(0.8f, mo[el], acc), bo);
                bool so = (vo >= TH);
                cnt[el] += so ? 1.f : 0.f;
                mo[el] = so ? 0.f : vo;
            }
        }

        out[g] = make_float2(cnt[0] * 0.0625f, cnt[1] * 0.0625f);

        g = gn;
        xx = xn;
    }
}

// Host-side replica of the device fp32 iteration (volatile blocks FMA contraction).
static float host_sim(float c, int n) {
    volatile float u = 0.f;
    for (int k = 0; k < n; k++) { volatile float t = 0.8f * u; u = t + c; }
    return u;
}

extern "C" void kernel_launch(void* const* d_in, const int* in_sizes, int n_in,
                              void* d_out, int out_size) {
    const float4* x2  = (const float4*)d_in[0];
    const float* W_ih = (const float*)d_in[1];
    const float* b_ih = (const float*)d_in[2];
    const float* W_hh = (const float*)d_in[3];
    const float* b_hh = (const float*)d_in[4];
    const float* W_ho = (const float*)d_in[5];
    const float* b_ho = (const float*)d_in[6];

    int B = in_sizes[0] / 2;
    int NP = B / 2;

    Params P;
    // Exact breakpoints via bitwise bisection (monotone in float bits on [0.05, 4]).
    for (int n = 1; n <= 16; n++) {
        float flo = 0.05f, fhi = 4.0f;
        unsigned lo, hi;
        memcpy(&lo, &flo, 4); memcpy(&hi, &fhi, 4);
        while (hi - lo > 1u) {
            unsigned mid = lo + (hi - lo) / 2;
            float fm; memcpy(&fm, &mid, 4);
            if (host_sim(fm, n) >= TH) hi = mid; else lo = mid;
        }
        memcpy(&P.tt[n - 1], &hi, 4);
    }
    for (int n1 = 0; n1 < 17; n1++) {
        unsigned w[4] = {0u, 0u, 0u, 0u};
        int n = n1 + 1;
        if (n <= 16)
            for (int t = 0; t < 16; t++)
                if ((t + 1) % n == 0) w[t >> 2] |= 1u << (8 * (t & 3));
        P.SPb[n1] = make_uint4(w[0], w[1], w[2], w[3]);
    }

    cudaFuncSetAttribute(snn_kernel,
                         cudaFuncAttributeMaxDynamicSharedMemorySize, SMEM_BYTES);

    snn_kernel<<<296, 256, SMEM_BYTES>>>(x2, W_ih, b_ih, W_hh, b_hh, W_ho, b_ho,
                                         (float2*)d_out, NP, P);
}